// round 1
// baseline (speedup 1.0000x reference)
#include <cuda_runtime.h>

static constexpr int NTOK = 32768;   // 8 * 4096
static constexpr int DIM  = 512;
static constexpr int HID  = 2048;
static constexpr int NEXP = 8;
static constexpr int MAXE = 2 * NTOK;   // max routed entries (K=2)

// ---- scratch (static device globals; no runtime allocation) ----
__device__ int   g_counts[NEXP];
__device__ int   g_offsets[NEXP + 1];
__device__ int   g_cursors[NEXP];
__device__ int   g_tok[MAXE];
__device__ float g_w[MAXE];
__device__ float g_h[(long long)MAXE * HID];   // 512 MB hidden activations

// ---------------- routing ----------------
__global__ void k_zero() {
    if (threadIdx.x < NEXP) g_counts[threadIdx.x] = 0;
}

__global__ void k_count(const int* __restrict__ assign) {
    int t = blockIdx.x * blockDim.x + threadIdx.x;
    if (t >= NTOK) return;
    int a0 = assign[2 * t], a1 = assign[2 * t + 1];
    atomicAdd(&g_counts[a0], 1);
    if (a1 != a0) atomicAdd(&g_counts[a1], 1);
}

__global__ void k_scan() {
    int off = 0;
    for (int e = 0; e < NEXP; e++) {
        g_offsets[e] = off;
        g_cursors[e] = off;
        off += g_counts[e];
    }
    g_offsets[NEXP] = off;
}

__global__ void k_place(const int* __restrict__ assign) {
    int t = blockIdx.x * blockDim.x + threadIdx.x;
    if (t >= NTOK) return;
    int a0 = assign[2 * t], a1 = assign[2 * t + 1];
    if (a0 == a1) {
        int p = atomicAdd(&g_cursors[a0], 1);
        g_tok[p] = t; g_w[p] = 1.0f;
    } else {
        int p = atomicAdd(&g_cursors[a0], 1);
        g_tok[p] = t; g_w[p] = 0.5f;
        int q = atomicAdd(&g_cursors[a1], 1);
        g_tok[q] = t; g_w[q] = 0.5f;
    }
}

// ---------------- GEMM1: h = relu(x[g_tok] @ W1[e] + b1[e]) ----------------
// Tile 128x128x8, 256 threads, 8x8 microtile per thread.
__global__ __launch_bounds__(256) void k_gemm1(
    const float* __restrict__ x,
    const float* __restrict__ W1,
    const float* __restrict__ b1)
{
    int e = blockIdx.z;
    int seg0 = g_offsets[e], seg1 = g_offsets[e + 1];
    int m0 = seg0 + blockIdx.y * 128;
    if (m0 >= seg1) return;
    int n0 = blockIdx.x * 128;

    __shared__ __align__(16) float As[8][128];   // [k][m] (transposed)
    __shared__ __align__(16) float Bs[8][128];   // [k][n]

    int tid = threadIdx.x;
    int tx = tid & 15, ty = tid >> 4;

    // A-load mapping: 128 rows x 8 k, float4 per thread
    int arow = tid >> 1;
    int ak   = (tid & 1) * 4;
    int am   = min(m0 + arow, seg1 - 1);
    const float* aptr = x + (long long)g_tok[am] * DIM + ak;

    // B-load mapping: 8 k-rows x 128 n, float4 per thread
    int brow = tid >> 5;
    int bcol = (tid & 31) * 4;
    const float* bptr = W1 + (long long)e * DIM * HID + (long long)brow * HID + n0 + bcol;

    float acc[8][8];
    #pragma unroll
    for (int i = 0; i < 8; i++)
        #pragma unroll
        for (int j = 0; j < 8; j++) acc[i][j] = 0.0f;

    for (int k0 = 0; k0 < DIM; k0 += 8) {
        float4 av = *(const float4*)(aptr + k0);
        float4 bv = *(const float4*)(bptr + (long long)k0 * HID);
        __syncthreads();
        As[ak + 0][arow] = av.x;
        As[ak + 1][arow] = av.y;
        As[ak + 2][arow] = av.z;
        As[ak + 3][arow] = av.w;
        *(float4*)&Bs[brow][bcol] = bv;
        __syncthreads();
        #pragma unroll
        for (int kk = 0; kk < 8; kk++) {
            float a[8], b[8];
            *(float4*)&a[0] = *(const float4*)&As[kk][ty * 8];
            *(float4*)&a[4] = *(const float4*)&As[kk][ty * 8 + 4];
            *(float4*)&b[0] = *(const float4*)&Bs[kk][tx * 8];
            *(float4*)&b[4] = *(const float4*)&Bs[kk][tx * 8 + 4];
            #pragma unroll
            for (int i = 0; i < 8; i++)
                #pragma unroll
                for (int j = 0; j < 8; j++)
                    acc[i][j] = fmaf(a[i], b[j], acc[i][j]);
        }
    }

    float bias[8];
    const float* b1p = b1 + (long long)e * HID + n0 + tx * 8;
    *(float4*)&bias[0] = *(const float4*)(b1p);
    *(float4*)&bias[4] = *(const float4*)(b1p + 4);

    #pragma unroll
    for (int i = 0; i < 8; i++) {
        int gm = m0 + ty * 8 + i;
        if (gm < seg1) {
            float* hp = g_h + (long long)gm * HID + n0 + tx * 8;
            float4 v0, v1;
            v0.x = fmaxf(acc[i][0] + bias[0], 0.0f);
            v0.y = fmaxf(acc[i][1] + bias[1], 0.0f);
            v0.z = fmaxf(acc[i][2] + bias[2], 0.0f);
            v0.w = fmaxf(acc[i][3] + bias[3], 0.0f);
            v1.x = fmaxf(acc[i][4] + bias[4], 0.0f);
            v1.y = fmaxf(acc[i][5] + bias[5], 0.0f);
            v1.z = fmaxf(acc[i][6] + bias[6], 0.0f);
            v1.w = fmaxf(acc[i][7] + bias[7], 0.0f);
            *(float4*)(hp)     = v0;
            *(float4*)(hp + 4) = v1;
        }
    }
}

// ---------------- GEMM2: out[tok] += (h @ W2[e] + b2[e]) * w ----------------
__global__ __launch_bounds__(256) void k_gemm2(
    const float* __restrict__ W2,
    const float* __restrict__ b2,
    float* __restrict__ out)
{
    int e = blockIdx.z;
    int seg0 = g_offsets[e], seg1 = g_offsets[e + 1];
    int m0 = seg0 + blockIdx.y * 128;
    if (m0 >= seg1) return;
    int n0 = blockIdx.x * 128;

    __shared__ __align__(16) float As[8][128];
    __shared__ __align__(16) float Bs[8][128];

    int tid = threadIdx.x;
    int tx = tid & 15, ty = tid >> 4;

    int arow = tid >> 1;
    int ak   = (tid & 1) * 4;
    int am   = min(m0 + arow, seg1 - 1);
    const float* aptr = g_h + (long long)am * HID + ak;

    int brow = tid >> 5;
    int bcol = (tid & 31) * 4;
    const float* bptr = W2 + (long long)e * HID * DIM + (long long)brow * DIM + n0 + bcol;

    float acc[8][8];
    #pragma unroll
    for (int i = 0; i < 8; i++)
        #pragma unroll
        for (int j = 0; j < 8; j++) acc[i][j] = 0.0f;

    for (int k0 = 0; k0 < HID; k0 += 8) {
        float4 av = *(const float4*)(aptr + k0);
        float4 bv = *(const float4*)(bptr + (long long)k0 * DIM);
        __syncthreads();
        As[ak + 0][arow] = av.x;
        As[ak + 1][arow] = av.y;
        As[ak + 2][arow] = av.z;
        As[ak + 3][arow] = av.w;
        *(float4*)&Bs[brow][bcol] = bv;
        __syncthreads();
        #pragma unroll
        for (int kk = 0; kk < 8; kk++) {
            float a[8], b[8];
            *(float4*)&a[0] = *(const float4*)&As[kk][ty * 8];
            *(float4*)&a[4] = *(const float4*)&As[kk][ty * 8 + 4];
            *(float4*)&b[0] = *(const float4*)&Bs[kk][tx * 8];
            *(float4*)&b[4] = *(const float4*)&Bs[kk][tx * 8 + 4];
            #pragma unroll
            for (int i = 0; i < 8; i++)
                #pragma unroll
                for (int j = 0; j < 8; j++)
                    acc[i][j] = fmaf(a[i], b[j], acc[i][j]);
        }
    }

    float bias[8];
    const float* b2p = b2 + (long long)e * DIM + n0 + tx * 8;
    *(float4*)&bias[0] = *(const float4*)(b2p);
    *(float4*)&bias[4] = *(const float4*)(b2p + 4);

    #pragma unroll
    for (int i = 0; i < 8; i++) {
        int gm = m0 + ty * 8 + i;
        if (gm < seg1) {
            float w = g_w[gm];
            int tok = g_tok[gm];
            float* op = out + (long long)tok * DIM + n0 + tx * 8;
            #pragma unroll
            for (int j = 0; j < 8; j++)
                atomicAdd(op + j, (acc[i][j] + bias[j]) * w);
        }
    }
}

// ---------------- launch ----------------
extern "C" void kernel_launch(void* const* d_in, const int* in_sizes, int n_in,
                              void* d_out, int out_size)
{
    const float* x      = (const float*)d_in[0];
    const int*   assign = (const int*)d_in[1];
    const float* W1     = (const float*)d_in[2];
    const float* b1     = (const float*)d_in[3];
    const float* W2     = (const float*)d_in[4];
    const float* b2     = (const float*)d_in[5];
    float* out = (float*)d_out;

    cudaMemsetAsync(out, 0, (size_t)out_size * sizeof(float), 0);

    k_zero<<<1, 32>>>();
    k_count<<<NTOK / 256, 256>>>(assign);
    k_scan<<<1, 1>>>();
    k_place<<<NTOK / 256, 256>>>(assign);

    dim3 g1(HID / 128, (NTOK + 127) / 128, NEXP);   // (16, 256, 8)
    k_gemm1<<<g1, 256>>>(x, W1, b1);

    dim3 g2(DIM / 128, (NTOK + 127) / 128, NEXP);   // (4, 256, 8)
    k_gemm2<<<g2, 256>>>(W2, b2, out);
}

// round 3
// speedup vs baseline: 2.1644x; 2.1644x over previous
#include <cuda_runtime.h>
#include <cstdint>

static constexpr int NTOK = 32768;   // 8 * 4096
static constexpr int DIM  = 512;
static constexpr int HID  = 2048;
static constexpr int NEXP = 8;
static constexpr int MAXE = 2 * NTOK;

// GEMM tiling
static constexpr int BM = 128, BN = 256, BK = 32;
static constexpr int ASTRIDE = 36;    // floats per A smem row  (36 % 32 == 4 -> conflict-free frags)
static constexpr int BSTRIDE = 264;   // floats per B smem row  (264 % 32 == 8 -> conflict-free frags)
static constexpr int A_FLOATS = BM * ASTRIDE;       // 4608
static constexpr int B_FLOATS = BK * BSTRIDE;       // 8448
static constexpr int STAGES = 3;
static constexpr int SMEM_BYTES = (STAGES * A_FLOATS + STAGES * B_FLOATS) * 4;  // 156672

// ---------------- scratch ----------------
__device__ int   g_counts[NEXP];
__device__ int   g_offsets[NEXP + 1];
__device__ int   g_cursors[NEXP];
__device__ int   g_tok[MAXE];
__device__ float g_w[MAXE];
__device__ int   g_cnt[NTOK];
__device__ int   g_pos[2 * NTOK];
__device__ float g_h[(long long)MAXE * HID];   // 512 MB hidden
__device__ float g_y[(long long)MAXE * DIM];   // 128 MB per-entry output

// ---------------- helpers ----------------
__device__ __forceinline__ uint32_t smem_u32(const void* p) {
    uint32_t a;
    asm("{ .reg .u64 t; cvta.to.shared.u64 t, %1; cvt.u32.u64 %0, t; }" : "=r"(a) : "l"(p));
    return a;
}
__device__ __forceinline__ void cp16(uint32_t daddr, const void* gptr) {
    asm volatile("cp.async.cg.shared.global [%0], [%1], 16;" :: "r"(daddr), "l"(gptr) : "memory");
}
__device__ __forceinline__ uint32_t to_tf32(float f) {
    uint32_t u;
    asm("cvt.rna.tf32.f32 %0, %1;" : "=r"(u) : "f"(f));
    return u;
}
__device__ __forceinline__ void mma1688(float* c, const uint32_t* a, const uint32_t* b) {
    asm volatile(
        "mma.sync.aligned.m16n8k8.row.col.f32.tf32.tf32.f32 "
        "{%0,%1,%2,%3}, {%4,%5,%6,%7}, {%8,%9}, {%0,%1,%2,%3};"
        : "+f"(c[0]), "+f"(c[1]), "+f"(c[2]), "+f"(c[3])
        : "r"(a[0]), "r"(a[1]), "r"(a[2]), "r"(a[3]), "r"(b[0]), "r"(b[1]));
}

// ---------------- routing ----------------
__global__ void k_zero() {
    if (threadIdx.x < NEXP) g_counts[threadIdx.x] = 0;
}
__global__ void k_count(const int* __restrict__ assign) {
    int t = blockIdx.x * blockDim.x + threadIdx.x;
    if (t >= NTOK) return;
    int a0 = assign[2 * t], a1 = assign[2 * t + 1];
    atomicAdd(&g_counts[a0], 1);
    if (a1 != a0) atomicAdd(&g_counts[a1], 1);
}
__global__ void k_scan() {
    int off = 0;
    for (int e = 0; e < NEXP; e++) {
        g_offsets[e] = off;
        g_cursors[e] = off;
        off += g_counts[e];
    }
    g_offsets[NEXP] = off;
}
__global__ void k_place(const int* __restrict__ assign) {
    int t = blockIdx.x * blockDim.x + threadIdx.x;
    if (t >= NTOK) return;
    int a0 = assign[2 * t], a1 = assign[2 * t + 1];
    if (a0 == a1) {
        int p = atomicAdd(&g_cursors[a0], 1);
        g_tok[p] = t; g_w[p] = 1.0f;
        g_pos[2 * t] = p; g_cnt[t] = 1;
    } else {
        int p = atomicAdd(&g_cursors[a0], 1);
        g_tok[p] = t; g_w[p] = 0.5f;
        int q = atomicAdd(&g_cursors[a1], 1);
        g_tok[q] = t; g_w[q] = 0.5f;
        g_pos[2 * t] = p; g_pos[2 * t + 1] = q; g_cnt[t] = 2;
    }
}

// ---------------- tf32 mma.sync GEMM ----------------
// Block 128x256x32, 8 warps (2 m x 4 n), warp tile 64x64, mma m16n8k8 tf32.
// G1: g_h = relu(x[g_tok] @ W1[e] + b1[e])      KTOT=512,  NTOT=2048
// G2: g_y = (g_h @ W2[e] + b2[e]) * g_w         KTOT=2048, NTOT=512
template <int KTOT, bool G1>
__global__ void __launch_bounds__(256) k_gemm(const float* __restrict__ Asrc_g,
                                              const float* __restrict__ W,
                                              const float* __restrict__ bias)
{
    constexpr int NTOT = G1 ? HID : DIM;
    constexpr int CH = KTOT / BK;

    extern __shared__ float sm[];

    int e = blockIdx.z;
    int seg0 = g_offsets[e], seg1 = g_offsets[e + 1];
    int m0 = seg0 + blockIdx.y * BM;
    if (m0 >= seg1) return;
    int n0 = blockIdx.x * BN;

    const float* Asrc = G1 ? Asrc_g : (const float*)g_h;

    int tid = threadIdx.x;
    int lane = tid & 31, wid = tid >> 5;
    int warp_m = wid & 1, warp_n = wid >> 1;

    // ---- cp.async source/dest mapping ----
    // A: 128 rows x 32 floats; 2 threads/row, 4x16B each
    int ar_ld = tid >> 1;
    int gmr = min(m0 + ar_ld, seg1 - 1);
    long long srow = G1 ? (long long)g_tok[gmr] : (long long)gmr;
    const float* aSrc = Asrc + srow * KTOT + (tid & 1) * 16;
    uint32_t aDst = smem_u32(sm) + (uint32_t)(ar_ld * ASTRIDE + (tid & 1) * 16) * 4u;

    // B: 32 rows x 256 floats; 8 threads/row, 8x16B each
    int br_ld = tid >> 3;
    const float* bSrc = W + (long long)e * KTOT * NTOT + (long long)br_ld * NTOT + n0 + (tid & 7) * 32;
    uint32_t bDst = smem_u32(sm + STAGES * A_FLOATS) + (uint32_t)(br_ld * BSTRIDE + (tid & 7) * 32) * 4u;

    auto load_chunk = [&](int c, int s) {
        const float* a = aSrc + c * BK;
        uint32_t ad = aDst + (uint32_t)(s * A_FLOATS) * 4u;
        #pragma unroll
        for (int i = 0; i < 4; i++) cp16(ad + i * 16, a + i * 4);
        const float* b = bSrc + (long long)c * BK * NTOT;
        uint32_t bd = bDst + (uint32_t)(s * B_FLOATS) * 4u;
        #pragma unroll
        for (int i = 0; i < 8; i++) cp16(bd + i * 16, b + i * 4);
        asm volatile("cp.async.commit_group;" ::: "memory");
    };

    float acc[4][8][4];
    #pragma unroll
    for (int mi = 0; mi < 4; mi++)
        #pragma unroll
        for (int nj = 0; nj < 8; nj++)
            #pragma unroll
            for (int q = 0; q < 4; q++) acc[mi][nj][q] = 0.0f;

    // prologue: 2 chunks in flight
    load_chunk(0, 0);
    load_chunk(1, 1);

    int arow = warp_m * 64 + (lane >> 2);
    int acol = lane & 3;
    int bcol = warp_n * 64 + (lane >> 2);
    int brow = lane & 3;

    for (int c = 0; c < CH; c++) {
        int s = c % STAGES;
        if (c + 1 < CH) asm volatile("cp.async.wait_group 1;" ::: "memory");
        else            asm volatile("cp.async.wait_group 0;" ::: "memory");
        __syncthreads();

        const float* As = sm + s * A_FLOATS;
        const float* Bs = sm + STAGES * A_FLOATS + s * B_FLOATS;

        #pragma unroll
        for (int kk = 0; kk < BK; kk += 8) {
            uint32_t af[4][4];
            #pragma unroll
            for (int mi = 0; mi < 4; mi++) {
                int r = arow + mi * 16;
                af[mi][0] = to_tf32(As[r * ASTRIDE + acol + kk]);
                af[mi][1] = to_tf32(As[(r + 8) * ASTRIDE + acol + kk]);
                af[mi][2] = to_tf32(As[r * ASTRIDE + acol + kk + 4]);
                af[mi][3] = to_tf32(As[(r + 8) * ASTRIDE + acol + kk + 4]);
            }
            uint32_t bf[8][2];
            #pragma unroll
            for (int nj = 0; nj < 8; nj++) {
                bf[nj][0] = to_tf32(Bs[(brow + kk) * BSTRIDE + bcol + nj * 8]);
                bf[nj][1] = to_tf32(Bs[(brow + kk + 4) * BSTRIDE + bcol + nj * 8]);
            }
            #pragma unroll
            for (int mi = 0; mi < 4; mi++)
                #pragma unroll
                for (int nj = 0; nj < 8; nj++)
                    mma1688(acc[mi][nj], af[mi], bf[nj]);
        }

        __syncthreads();
        if (c + 2 < CH) load_chunk(c + 2, (c + 2) % STAGES);
    }

    // ---- epilogue ----
    const float* bias_e = bias + (long long)e * NTOT;
    float2 bv[8];
    #pragma unroll
    for (int nj = 0; nj < 8; nj++) {
        int col = n0 + warp_n * 64 + nj * 8 + (lane & 3) * 2;
        bv[nj] = *(const float2*)(bias_e + col);
    }

    #pragma unroll
    for (int mi = 0; mi < 4; mi++) {
        int r0 = m0 + warp_m * 64 + mi * 16 + (lane >> 2);
        int r1 = r0 + 8;
        bool ok0 = r0 < seg1, ok1 = r1 < seg1;
        float w0 = 1.0f, w1 = 1.0f;
        if (!G1) {
            w0 = ok0 ? g_w[r0] : 0.0f;
            w1 = ok1 ? g_w[r1] : 0.0f;
        }
        float* d0 = (G1 ? g_h : g_y) + (long long)r0 * NTOT;
        float* d1 = (G1 ? g_h : g_y) + (long long)r1 * NTOT;
        #pragma unroll
        for (int nj = 0; nj < 8; nj++) {
            int col = n0 + warp_n * 64 + nj * 8 + (lane & 3) * 2;
            float2 v0, v1;
            if (G1) {
                v0.x = fmaxf(acc[mi][nj][0] + bv[nj].x, 0.0f);
                v0.y = fmaxf(acc[mi][nj][1] + bv[nj].y, 0.0f);
                v1.x = fmaxf(acc[mi][nj][2] + bv[nj].x, 0.0f);
                v1.y = fmaxf(acc[mi][nj][3] + bv[nj].y, 0.0f);
            } else {
                v0.x = (acc[mi][nj][0] + bv[nj].x) * w0;
                v0.y = (acc[mi][nj][1] + bv[nj].y) * w0;
                v1.x = (acc[mi][nj][2] + bv[nj].x) * w1;
                v1.y = (acc[mi][nj][3] + bv[nj].y) * w1;
            }
            if (ok0) *(float2*)(d0 + col) = v0;
            if (ok1) *(float2*)(d1 + col) = v1;
        }
    }
}

// ---------------- per-token gather ----------------
__global__ void k_gather(float* __restrict__ out) {
    int t = blockIdx.x;
    int c = threadIdx.x;   // 128 threads * float4 = 512 floats
    int cnt = g_cnt[t];
    int p0 = g_pos[2 * t];
    float4 v = ((const float4*)(g_y + (long long)p0 * DIM))[c];
    if (cnt == 2) {
        int p1 = g_pos[2 * t + 1];
        float4 u = ((const float4*)(g_y + (long long)p1 * DIM))[c];
        v.x += u.x; v.y += u.y; v.z += u.z; v.w += u.w;
    }
    ((float4*)(out + (long long)t * DIM))[c] = v;
}

// ---------------- launch ----------------
extern "C" void kernel_launch(void* const* d_in, const int* in_sizes, int n_in,
                              void* d_out, int out_size)
{
    const float* x      = (const float*)d_in[0];
    const int*   assign = (const int*)d_in[1];
    const float* W1     = (const float*)d_in[2];
    const float* b1     = (const float*)d_in[3];
    const float* W2     = (const float*)d_in[4];
    const float* b2     = (const float*)d_in[5];
    float* out = (float*)d_out;

    cudaFuncSetAttribute(k_gemm<DIM, true>,  cudaFuncAttributeMaxDynamicSharedMemorySize, SMEM_BYTES);
    cudaFuncSetAttribute(k_gemm<HID, false>, cudaFuncAttributeMaxDynamicSharedMemorySize, SMEM_BYTES);

    k_zero<<<1, 32>>>();
    k_count<<<NTOK / 256, 256>>>(assign);
    k_scan<<<1, 1>>>();
    k_place<<<NTOK / 256, 256>>>(assign);

    // GEMM1: entries x 512 @ 512 x 2048 -> g_h
    dim3 g1(HID / BN, MAXE / BM, NEXP);   // (8, 512, 8)
    k_gemm<DIM, true><<<g1, 256, SMEM_BYTES>>>(x, W1, b1);

    // GEMM2: entries x 2048 @ 2048 x 512 -> g_y
    dim3 g2(DIM / BN, MAXE / BM, NEXP);   // (2, 512, 8)
    k_gemm<HID, false><<<g2, 256, SMEM_BYTES>>>(nullptr, W2, b2);

    k_gather<<<NTOK, 128>>>(out);
}